// round 6
// baseline (speedup 1.0000x reference)
#include <cuda_runtime.h>
#include <cstddef>

// Problem constants
#define HH 256
#define WW 256
#define BB 16
#define CC 64
#define LL 256
#define HW 65536

typedef unsigned long long u64;

// ---------------- scratch (device globals; no allocation allowed) ----------
__device__ float  g_bufA[(size_t)BB * CC * HW];   // 268 MB
__device__ float  g_bufB[(size_t)BB * CC * HW];   // 268 MB
__device__ float2 g_G[(size_t)BB * HH * 21];
__device__ float2 g_delta[BB * LL];
__device__ float2 g_U[(size_t)BB * 21 * WW];
__device__ float  g_T[BB * CC * 9];
__device__ int    g_dy[LL];
__device__ int    g_dx[LL];
// Winograd-transformed weights U = G g G^T, layout [ic][oc][16]
__device__ float  g_wU[268288];

#define U_O0 0
#define U_O1 3072
#define U_O2 68608
#define U_O3 134144
#define U_O4 199680

// ---------------- helpers --------------------------------------------------
__device__ __forceinline__ u64 pk2(float lo, float hi) {
    u64 r;
    asm("mov.b64 %0, {%1,%2};" : "=l"(r) : "f"(lo), "f"(hi));
    return r;
}
__device__ __forceinline__ void upk2(u64 v, float& lo, float& hi) {
    asm("mov.b64 {%0,%1}, %2;" : "=f"(lo), "=f"(hi) : "l"(v));
}
__device__ __forceinline__ void ffma2(u64& d, u64 a, u64 b) {
    asm("fma.rn.f32x2 %0, %1, %2, %0;" : "+l"(d) : "l"(a), "l"(b));
}
__device__ __forceinline__ unsigned smem_u32(const void* p) {
    return (unsigned)__cvta_generic_to_shared(p);
}
__device__ __forceinline__ void cpa4(unsigned dst, const float* src, int cnt) {
    asm volatile("cp.async.ca.shared.global [%0], [%1], 4, %2;"
                 :: "r"(dst), "l"(src), "r"(cnt));
}
__device__ __forceinline__ void cpa16(unsigned dst, const float* src) {
    asm volatile("cp.async.cg.shared.global [%0], [%1], 16;"
                 :: "r"(dst), "l"(src));
}
__device__ __forceinline__ void cpcommit() { asm volatile("cp.async.commit_group;"); }
__device__ __forceinline__ void cpwait0()  { asm volatile("cp.async.wait_group 0;" ::: "memory"); }

// ---------------- prep: watermark indices + Winograd weight transforms -----
__global__ void prepU(const float* __restrict__ w0, const float* __restrict__ wk,
                      const float* __restrict__ wa, float* __restrict__ Uo)
{
    int n = blockIdx.x * 256 + threadIdx.x;
    if (n == 0) {
        int cnt = 0;
        for (int i = -10; i <= 10; i++)
            for (int j = -10; j <= 10; j++)
                if (i * i + j * j <= 100 && cnt < LL) { g_dy[cnt] = i; g_dx[cnt] = j; cnt++; }
    }
    if (n >= 16768) return;
    const float* src;
    float* dst;
    if (n < 192) {
        int ic = n / 64, oc = n - ic * 64;
        src = w0 + ((size_t)oc * 3 + ic) * 9;
        dst = Uo + U_O0 + ((size_t)ic * 64 + oc) * 16;
    } else if (n < 12480) {
        int m = n - 192, t = m / 4096, r = m - t * 4096;
        int ic = r / 64, oc = r - ic * 64;
        src = wk + (size_t)t * 36864 + ((size_t)oc * 64 + ic) * 9;
        dst = Uo + U_O1 + (size_t)t * 65536 + ((size_t)ic * 64 + oc) * 16;
    } else {
        int r = n - 12480;
        int ic = r / 64, oc = r - ic * 64;
        int cin = (ic < 64) ? 256 + ic : 320 + (ic - 64);
        src = wa + ((size_t)oc * 323 + cin) * 9;
        dst = Uo + U_O4 + ((size_t)ic * 64 + oc) * 16;
    }
    float g[3][3];
#pragma unroll
    for (int i = 0; i < 3; i++)
#pragma unroll
        for (int j = 0; j < 3; j++) g[i][j] = src[i * 3 + j];
    float a[4][3];
#pragma unroll
    for (int j = 0; j < 3; j++) {
        a[0][j] = g[0][j];
        a[1][j] = 0.5f * (g[0][j] + g[1][j] + g[2][j]);
        a[2][j] = 0.5f * (g[0][j] - g[1][j] + g[2][j]);
        a[3][j] = g[2][j];
    }
#pragma unroll
    for (int i = 0; i < 4; i++) {
        dst[i * 4 + 0] = a[i][0];
        dst[i * 4 + 1] = 0.5f * (a[i][0] + a[i][1] + a[i][2]);
        dst[i * 4 + 2] = 0.5f * (a[i][0] - a[i][1] + a[i][2]);
        dst[i * 4 + 3] = a[i][2];
    }
}

// ---------------- Winograd conv3x3 + BN + ReLU -----------------------------
#define SI_STRIDE 68

struct NoT {
    __device__ __forceinline__ float t(int, int, int) const { return 0.f; }
};

struct WaT {
    const float* T9;
    int cy0, cy1, cxA, cxB;
    __device__ __forceinline__ float t(int oc, int row, int col) const {
        int cy = row ? cy1 : cy0;
        int cx = col ? cxB : cxA;
        return T9[oc * 9 + cy * 3 + cx];
    }
};

struct SrcPlain {
    const float* base;   // in + b*CI*HW
    __device__ __forceinline__ const float* operator()(int c) const {
        return base + (size_t)c * HW;
    }
};

struct SrcWa {
    const float* enc;    // enc + b*CC*HW
    const float* img;    // img + b*3*HW
    __device__ __forceinline__ const float* operator()(int c) const {
        return (c < 64) ? enc + (size_t)c * HW
                        : img + (size_t)(c - 64) * HW;
    }
};

template <typename TSrc, typename TAdd>
__device__ __forceinline__ void convW_body(
    TSrc srcptr, int CI, const float* __restrict__ Uw,
    const float* __restrict__ bb, const float* __restrict__ gg,
    const float* __restrict__ bee, const float* __restrict__ mm,
    const float* __restrict__ vv, float* __restrict__ out, TAdd Tadd)
{
    const int w0 = blockIdx.x * 64, h0 = blockIdx.y * 2, b = blockIdx.z;
    const int tid = threadIdx.x, lane = tid & 31, wg = tid >> 5;
    const int obase = wg * 8;

    __shared__ __align__(16) float s_in[2][4 * SI_STRIDE];
    __shared__ __align__(16) float s_Uw[2][1024];

    const int u_a = tid / 66, j_a = tid - u_a * 66;
    const int idx_b = tid + 256;
    const int u_b = idx_b / 66, j_b = idx_b - u_b * 66;

    // per-thread staging source validity (loop-invariant)
    const int gy_a = h0 - 1 + u_a, gx_a = w0 - 1 + j_a;
    const bool v_a = (gy_a >= 0 && gy_a < HH && gx_a >= 0 && gx_a < WW);
    const size_t off_a = (size_t)(v_a ? gy_a : 0) * WW + (v_a ? gx_a : 0);
    const int gy_b = h0 - 1 + u_b, gx_b = w0 - 1 + j_b;
    const bool inr_b = (idx_b < 264);
    const bool v_b = inr_b && (gy_b >= 0 && gy_b < HH && gx_b >= 0 && gx_b < WW);
    const size_t off_b = (size_t)(v_b ? gy_b : 0) * WW + (v_b ? gx_b : 0);

    u64 acc[8][8];
#pragma unroll
    for (int o = 0; o < 8; o++)
#pragma unroll
        for (int k = 0; k < 8; k++) acc[o][k] = 0ull;

    // stage channel 0
    {
        const float* ip = srcptr(0);
        cpa4(smem_u32(&s_in[0][u_a * SI_STRIDE + j_a]), ip + off_a, v_a ? 4 : 0);
        if (inr_b)
            cpa4(smem_u32(&s_in[0][u_b * SI_STRIDE + j_b]), ip + off_b, v_b ? 4 : 0);
        cpa16(smem_u32(&s_Uw[0][tid * 4]), Uw + tid * 4);
        cpcommit();
    }

    for (int c = 0; c < CI; c++) {
        const int cur = c & 1;
        cpwait0();
        __syncthreads();
        if (c + 1 < CI) {
            const int nb = cur ^ 1;
            const float* ip = srcptr(c + 1);
            cpa4(smem_u32(&s_in[nb][u_a * SI_STRIDE + j_a]), ip + off_a, v_a ? 4 : 0);
            if (inr_b)
                cpa4(smem_u32(&s_in[nb][u_b * SI_STRIDE + j_b]), ip + off_b, v_b ? 4 : 0);
            cpa16(smem_u32(&s_Uw[nb][tid * 4]), Uw + (size_t)(c + 1) * 1024 + tid * 4);
            cpcommit();
        }

        // load 4x4 window, transform: V = Bt d B
        float d[4][4];
        {
            const float* si = s_in[cur] + 2 * lane;
#pragma unroll
            for (int u = 0; u < 4; u++) {
                float2 xa = *(const float2*)(si + u * SI_STRIDE);
                float2 xb = *(const float2*)(si + u * SI_STRIDE + 2);
                d[u][0] = xa.x; d[u][1] = xa.y; d[u][2] = xb.x; d[u][3] = xb.y;
            }
        }
#pragma unroll
        for (int j = 0; j < 4; j++) {
            float a0 = d[0][j], a1 = d[1][j], a2 = d[2][j], a3 = d[3][j];
            d[0][j] = a0 - a2;
            d[1][j] = a1 + a2;
            d[2][j] = a2 - a1;
            d[3][j] = a1 - a3;
        }
        u64 V2[8];
#pragma unroll
        for (int i = 0; i < 4; i++) {
            float a0 = d[i][0], a1 = d[i][1], a2 = d[i][2], a3 = d[i][3];
            V2[2 * i]     = pk2(a0 - a2, a1 + a2);
            V2[2 * i + 1] = pk2(a2 - a1, a1 - a3);
        }

#pragma unroll
        for (int o = 0; o < 8; o++) {
            const ulonglong2* Up = (const ulonglong2*)(s_Uw[cur] + (obase + o) * 16);
            ulonglong2 uA = Up[0], uB = Up[1], uC = Up[2], uD = Up[3];
            ffma2(acc[o][0], uA.x, V2[0]);
            ffma2(acc[o][1], uA.y, V2[1]);
            ffma2(acc[o][2], uB.x, V2[2]);
            ffma2(acc[o][3], uB.y, V2[3]);
            ffma2(acc[o][4], uC.x, V2[4]);
            ffma2(acc[o][5], uC.y, V2[5]);
            ffma2(acc[o][6], uD.x, V2[6]);
            ffma2(acc[o][7], uD.y, V2[7]);
        }
        __syncthreads();
    }

    // inverse transform Y = At M A, add const, BN, ReLU, store
#pragma unroll
    for (int o = 0; o < 8; o++) {
        int oc = obase + o;
        float m[16];
#pragma unroll
        for (int k = 0; k < 8; k++) upk2(acc[o][k], m[2 * k], m[2 * k + 1]);
        float z0[4], z1[4];
#pragma unroll
        for (int j = 0; j < 4; j++) {
            z0[j] = m[j] + m[4 + j] + m[8 + j];
            z1[j] = m[4 + j] - m[8 + j] - m[12 + j];
        }
        float y00 = z0[0] + z0[1] + z0[2];
        float y01 = z0[1] - z0[2] - z0[3];
        float y10 = z1[0] + z1[1] + z1[2];
        float y11 = z1[1] - z1[2] - z1[3];

        y00 += Tadd.t(oc, 0, 0); y01 += Tadd.t(oc, 0, 1);
        y10 += Tadd.t(oc, 1, 0); y11 += Tadd.t(oc, 1, 1);

        float s = gg[oc] * rsqrtf(vv[oc] + 1e-5f);
        float t = fmaf(s, bb[oc] - mm[oc], bee[oc]);
        float2 r0, r1;
        r0.x = fmaxf(fmaf(s, y00, t), 0.f);
        r0.y = fmaxf(fmaf(s, y01, t), 0.f);
        r1.x = fmaxf(fmaf(s, y10, t), 0.f);
        r1.y = fmaxf(fmaf(s, y11, t), 0.f);
        size_t base = ((size_t)(b * CC + oc) * HH + h0) * WW + w0 + 2 * lane;
        *(float2*)(out + base) = r0;
        *(float2*)(out + base + WW) = r1;
    }
}

__global__ void __launch_bounds__(256, 2)
convW(const float* __restrict__ in, int CI, const float* __restrict__ Uw,
      const float* __restrict__ bb, const float* __restrict__ gg,
      const float* __restrict__ bee, const float* __restrict__ mm,
      const float* __restrict__ vv, float* __restrict__ out)
{
    SrcPlain src;
    src.base = in + (size_t)blockIdx.z * CI * HW;
    convW_body(src, CI, Uw, bb, gg, bee, mm, vv, out, NoT());
}

__global__ void __launch_bounds__(256, 2)
convWa(const float* __restrict__ enc, const float* __restrict__ img,
       const float* __restrict__ Uw,
       const float* __restrict__ bb, const float* __restrict__ gg,
       const float* __restrict__ bee, const float* __restrict__ mm,
       const float* __restrict__ vv, float* __restrict__ out)
{
    const int b = blockIdx.z;
    __shared__ float s_T[576];
    for (int idx = threadIdx.x; idx < 576; idx += 256)
        s_T[idx] = g_T[(size_t)b * 576 + idx];
    __syncthreads();

    const int w0 = blockIdx.x * 64, h0 = blockIdx.y * 2;
    const int lane = threadIdx.x & 31;
    const int colA = w0 + 2 * lane, colB = colA + 1;
    WaT wt;
    wt.T9 = s_T;
    wt.cy0 = (h0 == 0) ? 0 : 1;
    wt.cy1 = (h0 + 1 == HH - 1) ? 2 : 1;
    wt.cxA = (colA == 0) ? 0 : ((colA == WW - 1) ? 2 : 1);
    wt.cxB = (colB == WW - 1) ? 2 : 1;

    SrcWa src;
    src.enc = enc + (size_t)b * CC * HW;
    src.img = img + (size_t)b * 3 * HW;
    convW_body(src, 67, Uw, bb, gg, bee, mm, vv, out, wt);
}

// ---------------- msg contribution T[b][o][case] ---------------------------
__global__ void msgT(const float* __restrict__ msg, const float* __restrict__ wa)
{
    int o = blockIdx.x, b = blockIdx.y, l = threadIdx.x;
    __shared__ float S[9][256];
    float m = msg[b * LL + l];
    const float* wp = wa + ((size_t)o * 323 + l) * 9;
#pragma unroll
    for (int k = 0; k < 9; k++) S[k][l] = m * wp[k];
    __syncthreads();
    for (int s = 128; s > 0; s >>= 1) {
        if (l < s) {
#pragma unroll
            for (int k = 0; k < 9; k++) S[k][l] += S[k][l + s];
        }
        __syncthreads();
    }
    if (l == 0) {
        float P[9];
#pragma unroll
        for (int k = 0; k < 9; k++) P[k] = S[k][0];
        for (int cy = 0; cy < 3; cy++)
            for (int cx = 0; cx < 3; cx++) {
                float t = 0.f;
                for (int ky = 0; ky < 3; ky++) {
                    if (!(cy == 1 || (cy == 0 && ky >= 1) || (cy == 2 && ky <= 1))) continue;
                    for (int kx = 0; kx < 3; kx++) {
                        if (!(cx == 1 || (cx == 0 && kx >= 1) || (cx == 2 && kx <= 1))) continue;
                        t += P[ky * 3 + kx];
                    }
                }
                g_T[((size_t)b * CC + o) * 9 + cy * 3 + cx] = t;
            }
    }
}

// ---------------- watermark: sparse-frequency fft edit ---------------------
__global__ void kG(const float* __restrict__ x)
{
    int h = blockIdx.x, b = blockIdx.y, lane = threadIdx.x;
    __shared__ float ct[256], st[256];
    for (int i = lane; i < 256; i += 32) {
        float s, c;
        sincosf(6.283185307179586f * (float)i / 256.f, &s, &c);
        ct[i] = c; st[i] = s;
    }
    __syncthreads();
    const float* xp = x + ((size_t)(b * CC) * HH + h) * WW;
    float gr[21], gi[21];
#pragma unroll
    for (int j = 0; j < 21; j++) { gr[j] = 0.f; gi[j] = 0.f; }
    for (int w = lane; w < WW; w += 32) {
        float v = xp[w];
#pragma unroll
        for (int j = 0; j < 21; j++) {
            int idx = ((118 + j) * w) & 255;
            gr[j] = fmaf(v, ct[idx], gr[j]);
            gi[j] = fmaf(-v, st[idx], gi[j]);
        }
    }
#pragma unroll
    for (int j = 0; j < 21; j++) {
        for (int off = 16; off; off >>= 1) {
            gr[j] += __shfl_down_sync(0xffffffffu, gr[j], off);
            gi[j] += __shfl_down_sync(0xffffffffu, gi[j], off);
        }
    }
    if (lane == 0) {
#pragma unroll
        for (int j = 0; j < 21; j++)
            g_G[((size_t)b * HH + h) * 21 + j] = make_float2(gr[j], gi[j]);
    }
}

__global__ void kF(const float* __restrict__ msg)
{
    int b = blockIdx.x, l = threadIdx.x;
    __shared__ float ct[256], st[256];
    {
        float s, c;
        sincosf(6.283185307179586f * (float)l / 256.f, &s, &c);
        ct[l] = c; st[l] = s;
    }
    __syncthreads();
    int dy = g_dy[l], dx = g_dx[l];
    int jx = dx + 10, yy = 128 + dy;
    float fr = 0.f, fi = 0.f;
    for (int h = 0; h < HH; h++) {
        float2 G = g_G[((size_t)b * HH + h) * 21 + jx];
        int idx = (yy * h) & 255;
        float c = ct[idx], s = st[idx];
        fr += G.x * c + G.y * s;
        fi += G.y * c - G.x * s;
    }
    float m = msg[b * LL + l];
    g_delta[b * LL + l] = make_float2(m - fr, m - fi);
}

__global__ void kU()
{
    int iy = blockIdx.x, b = blockIdx.y, w = threadIdx.x;
    __shared__ float ct[256], st[256], dr[256], di[256];
    __shared__ int sdx[256], sdy[256];
    {
        float s, c;
        sincosf(6.283185307179586f * (float)w / 256.f, &s, &c);
        ct[w] = c; st[w] = s;
        float2 d = g_delta[b * LL + w];
        dr[w] = d.x; di[w] = d.y;
        sdx[w] = g_dx[w]; sdy[w] = g_dy[w];
    }
    __syncthreads();
    float ur = 0.f, ui = 0.f;
    for (int l = 0; l < LL; l++) {
        if (sdy[l] + 10 == iy) {
            int idx = ((128 + sdx[l]) * w) & 255;
            float c = ct[idx], s = st[idx];
            ur += dr[l] * c - di[l] * s;
            ui += dr[l] * s + di[l] * c;
        }
    }
    g_U[((size_t)b * 21 + iy) * WW + w] = make_float2(ur, ui);
}

__global__ void kAdd(float* __restrict__ x)
{
    int h = blockIdx.x, b = blockIdx.y, w = threadIdx.x;
    __shared__ float ct[256], st[256];
    {
        float s, c;
        sincosf(6.283185307179586f * (float)w / 256.f, &s, &c);
        ct[w] = c; st[w] = s;
    }
    __syncthreads();
    float a = 0.f;
#pragma unroll
    for (int iy = 0; iy < 21; iy++) {
        int idx = ((118 + iy) * h) & 255;
        float2 U = g_U[((size_t)b * 21 + iy) * WW + w];
        a += U.x * ct[idx] - U.y * st[idx];
    }
    size_t off = ((size_t)(b * CC) * HH + h) * WW + w;
    x[off] += a * (1.f / 65536.f);
}

// ---------------- final 1x1 projection 64 -> 3 -----------------------------
__global__ void final1x1(const float* __restrict__ y, const float* __restrict__ wf,
                         const float* __restrict__ bf, float* __restrict__ out)
{
    int w = threadIdx.x, h = blockIdx.x, b = blockIdx.y;
    __shared__ float swf[192];
    __shared__ float sbf[3];
    if (threadIdx.x < 192) swf[threadIdx.x] = wf[threadIdx.x];
    if (threadIdx.x < 3) sbf[threadIdx.x] = bf[threadIdx.x];
    __syncthreads();
    float a0 = sbf[0], a1 = sbf[1], a2 = sbf[2];
    const float* yp = y + ((size_t)(b * CC) * HH + h) * WW + w;
#pragma unroll 8
    for (int c = 0; c < 64; c++) {
        float v = yp[(size_t)c * HW];
        a0 = fmaf(v, swf[c], a0);
        a1 = fmaf(v, swf[64 + c], a1);
        a2 = fmaf(v, swf[128 + c], a2);
    }
    size_t o = ((size_t)(b * 3) * HH + h) * WW + w;
    out[o] = a0;
    out[o + (size_t)HW] = a1;
    out[o + (size_t)2 * HW] = a2;
}

// ---------------- launcher -------------------------------------------------
extern "C" void kernel_launch(void* const* d_in, const int* in_sizes, int n_in,
                              void* d_out, int out_size)
{
    const float* image   = (const float*)d_in[0];
    const float* message = (const float*)d_in[1];
    const float* w0  = (const float*)d_in[2];
    const float* b0  = (const float*)d_in[3];
    const float* g0  = (const float*)d_in[4];
    const float* be0 = (const float*)d_in[5];
    const float* m0  = (const float*)d_in[6];
    const float* v0  = (const float*)d_in[7];
    const float* wk  = (const float*)d_in[8];
    const float* bk  = (const float*)d_in[9];
    const float* gk  = (const float*)d_in[10];
    const float* bek = (const float*)d_in[11];
    const float* mk  = (const float*)d_in[12];
    const float* vk  = (const float*)d_in[13];
    const float* wa  = (const float*)d_in[14];
    const float* ba  = (const float*)d_in[15];
    const float* ga  = (const float*)d_in[16];
    const float* bea = (const float*)d_in[17];
    const float* ma  = (const float*)d_in[18];
    const float* va  = (const float*)d_in[19];
    const float* wf  = (const float*)d_in[20];
    const float* bf  = (const float*)d_in[21];

    float* bufA = nullptr;
    float* bufB = nullptr;
    float* Uw = nullptr;
    cudaGetSymbolAddress((void**)&bufA, g_bufA);
    cudaGetSymbolAddress((void**)&bufB, g_bufB);
    cudaGetSymbolAddress((void**)&Uw, g_wU);

    // launch 1: all prep (indices + weight transforms)
    prepU<<<66, 256>>>(w0, wk, wa, Uw);
    // launch 2: message contribution (independent of convs)
    msgT<<<dim3(64, BB), 256>>>(message, wa);

    dim3 cgrid(WW / 64, HH / 2, BB);
    // launches 3-6 (launch 6 = conv layer 3, captured by ncu -s 5)
    convW<<<cgrid, 256>>>(image, 3, Uw + U_O0, b0, g0, be0, m0, v0, bufA);
    convW<<<cgrid, 256>>>(bufA, 64, Uw + U_O1, bk,       gk,       bek,       mk,       vk,       bufB);
    convW<<<cgrid, 256>>>(bufB, 64, Uw + U_O2, bk + 64,  gk + 64,  bek + 64,  mk + 64,  vk + 64,  bufA);
    convW<<<cgrid, 256>>>(bufA, 64, Uw + U_O3, bk + 128, gk + 128, bek + 128, mk + 128, vk + 128, bufB);

    // watermark (modifies channel 0 of bufB in place)
    kG<<<dim3(HH, BB), 32>>>(bufB);
    kF<<<BB, 256>>>(message);
    kU<<<dim3(21, BB), 256>>>();
    kAdd<<<dim3(HH, BB), 256>>>(bufB);

    convWa<<<cgrid, 256>>>(bufB, image, Uw + U_O4, ba, ga, bea, ma, va, bufA);

    final1x1<<<dim3(HH, BB), 256>>>(bufA, wf, bf, (float*)d_out);
}

// round 7
// speedup vs baseline: 3.2168x; 3.2168x over previous
#include <cuda_runtime.h>
#include <cstddef>

// Problem constants
#define HH 256
#define WW 256
#define BB 16
#define CC 64
#define LL 256
#define HW 65536

typedef unsigned long long u64;

// ---------------- scratch (device globals; no allocation allowed) ----------
__device__ float  g_bufA[(size_t)BB * CC * HW];   // 268 MB
__device__ float  g_bufB[(size_t)BB * CC * HW];   // 268 MB
__device__ float2 g_G[(size_t)BB * HH * 21];
__device__ float2 g_delta[BB * LL];
__device__ float2 g_U[(size_t)BB * 21 * WW];
__device__ float  g_T[BB * CC * 9];
__device__ int    g_dy[LL];
__device__ int    g_dx[LL];
// Winograd-transformed weights U = G g G^T, layout [ic][oc][16]
__device__ float  g_wU[268288];

#define U_O0 0
#define U_O1 3072
#define U_O2 68608
#define U_O3 134144
#define U_O4 199680

// ---------------- helpers --------------------------------------------------
__device__ __forceinline__ u64 pk2(float lo, float hi) {
    u64 r;
    asm("mov.b64 %0, {%1,%2};" : "=l"(r) : "f"(lo), "f"(hi));
    return r;
}
__device__ __forceinline__ void upk2(u64 v, float& lo, float& hi) {
    asm("mov.b64 {%0,%1}, %2;" : "=f"(lo), "=f"(hi) : "l"(v));
}
__device__ __forceinline__ void ffma2(u64& d, u64 a, u64 b) {
    asm("fma.rn.f32x2 %0, %1, %2, %0;" : "+l"(d) : "l"(a), "l"(b));
}
__device__ __forceinline__ unsigned smem_u32(const void* p) {
    return (unsigned)__cvta_generic_to_shared(p);
}
__device__ __forceinline__ void cpa4(unsigned dst, const float* src, int cnt) {
    asm volatile("cp.async.ca.shared.global [%0], [%1], 4, %2;"
                 :: "r"(dst), "l"(src), "r"(cnt));
}
__device__ __forceinline__ void cpa16(unsigned dst, const float* src) {
    asm volatile("cp.async.cg.shared.global [%0], [%1], 16;"
                 :: "r"(dst), "l"(src));
}
__device__ __forceinline__ void cpcommit() { asm volatile("cp.async.commit_group;"); }
__device__ __forceinline__ void cpwaitg2() {
    asm volatile("cp.async.wait_group 2;" ::: "memory");
}

// ---------------- prep: watermark indices + Winograd weight transforms -----
__global__ void prepU(const float* __restrict__ w0, const float* __restrict__ wk,
                      const float* __restrict__ wa, float* __restrict__ Uo)
{
    int n = blockIdx.x * 256 + threadIdx.x;
    if (n == 0) {
        int cnt = 0;
        for (int i = -10; i <= 10; i++)
            for (int j = -10; j <= 10; j++)
                if (i * i + j * j <= 100 && cnt < LL) { g_dy[cnt] = i; g_dx[cnt] = j; cnt++; }
    }
    if (n >= 16768) return;
    const float* src;
    float* dst;
    if (n < 192) {
        int ic = n / 64, oc = n - ic * 64;
        src = w0 + ((size_t)oc * 3 + ic) * 9;
        dst = Uo + U_O0 + ((size_t)ic * 64 + oc) * 16;
    } else if (n < 12480) {
        int m = n - 192, t = m / 4096, r = m - t * 4096;
        int ic = r / 64, oc = r - ic * 64;
        src = wk + (size_t)t * 36864 + ((size_t)oc * 64 + ic) * 9;
        dst = Uo + U_O1 + (size_t)t * 65536 + ((size_t)ic * 64 + oc) * 16;
    } else {
        int r = n - 12480;
        int ic = r / 64, oc = r - ic * 64;
        int cin = (ic < 64) ? 256 + ic : 320 + (ic - 64);
        src = wa + ((size_t)oc * 323 + cin) * 9;
        dst = Uo + U_O4 + ((size_t)ic * 64 + oc) * 16;
    }
    float g[3][3];
#pragma unroll
    for (int i = 0; i < 3; i++)
#pragma unroll
        for (int j = 0; j < 3; j++) g[i][j] = src[i * 3 + j];
    float a[4][3];
#pragma unroll
    for (int j = 0; j < 3; j++) {
        a[0][j] = g[0][j];
        a[1][j] = 0.5f * (g[0][j] + g[1][j] + g[2][j]);
        a[2][j] = 0.5f * (g[0][j] - g[1][j] + g[2][j]);
        a[3][j] = g[2][j];
    }
#pragma unroll
    for (int i = 0; i < 4; i++) {
        dst[i * 4 + 0] = a[i][0];
        dst[i * 4 + 1] = 0.5f * (a[i][0] + a[i][1] + a[i][2]);
        dst[i * 4 + 2] = 0.5f * (a[i][0] - a[i][1] + a[i][2]);
        dst[i * 4 + 3] = a[i][2];
    }
}

// ---------------- Winograd conv3x3 + BN + ReLU -----------------------------
#define SI_STRIDE 68
#define NST 4

struct NoT {
    __device__ __forceinline__ float t(int, int, int) const { return 0.f; }
};

struct WaT {
    const float* T9;
    int cy0, cy1, cxA, cxB;
    __device__ __forceinline__ float t(int oc, int row, int col) const {
        int cy = row ? cy1 : cy0;
        int cx = col ? cxB : cxA;
        return T9[oc * 9 + cy * 3 + cx];
    }
};

struct SrcPlain {
    const float* base;
    __device__ __forceinline__ const float* operator()(int c) const {
        return base + (size_t)c * HW;
    }
};

struct SrcWa {
    const float* enc;
    const float* img;
    __device__ __forceinline__ const float* operator()(int c) const {
        return (c < 64) ? enc + (size_t)c * HW
                        : img + (size_t)(c - 64) * HW;
    }
};

template <typename TSrc, typename TAdd>
__device__ __forceinline__ void convW_body(
    TSrc srcptr, int CI, const float* __restrict__ Uw,
    const float* __restrict__ bb, const float* __restrict__ gg,
    const float* __restrict__ bee, const float* __restrict__ mm,
    const float* __restrict__ vv, float* __restrict__ out, TAdd Tadd)
{
    const int w0 = blockIdx.x * 64, h0 = blockIdx.y * 2, b = blockIdx.z;
    const int tid = threadIdx.x, lane = tid & 31, wg = tid >> 5;
    const int obase = wg * 8;

    __shared__ __align__(16) float s_in[NST][4 * SI_STRIDE];
    __shared__ __align__(16) float s_Uw[NST][1024];

    const int u_a = tid / 66, j_a = tid - u_a * 66;
    const int idx_b = tid + 256;
    const int u_b = idx_b / 66, j_b = idx_b - u_b * 66;

    const int gy_a = h0 - 1 + u_a, gx_a = w0 - 1 + j_a;
    const bool v_a = (gy_a >= 0 && gy_a < HH && gx_a >= 0 && gx_a < WW);
    const size_t off_a = (size_t)(v_a ? gy_a : 0) * WW + (v_a ? gx_a : 0);
    const int gy_b = h0 - 1 + u_b, gx_b = w0 - 1 + j_b;
    const bool inr_b = (idx_b < 264);
    const bool v_b = inr_b && (gy_b >= 0 && gy_b < HH && gx_b >= 0 && gx_b < WW);
    const size_t off_b = (size_t)(v_b ? gy_b : 0) * WW + (v_b ? gx_b : 0);

    u64 acc[8][8];
#pragma unroll
    for (int o = 0; o < 8; o++)
#pragma unroll
        for (int k = 0; k < 8; k++) acc[o][k] = 0ull;

    // prologue: prefetch channels 0..2 (CI >= 3 always)
#pragma unroll
    for (int p = 0; p < 3; p++) {
        const float* ip = srcptr(p);
        cpa4(smem_u32(&s_in[p][u_a * SI_STRIDE + j_a]), ip + off_a, v_a ? 4 : 0);
        if (inr_b)
            cpa4(smem_u32(&s_in[p][u_b * SI_STRIDE + j_b]), ip + off_b, v_b ? 4 : 0);
        cpa16(smem_u32(&s_Uw[p][tid * 4]), Uw + (size_t)p * 1024 + tid * 4);
        cpcommit();
    }

    for (int c = 0; c < CI; c++) {
        const int cur = c & (NST - 1);
        cpwaitg2();            // groups for stages <= c complete
        __syncthreads();       // data visible block-wide; stage (c+3)%NST free
        {
            const int cp = c + 3;
            if (cp < CI) {
                const int nb = cp & (NST - 1);
                const float* ip = srcptr(cp);
                cpa4(smem_u32(&s_in[nb][u_a * SI_STRIDE + j_a]), ip + off_a, v_a ? 4 : 0);
                if (inr_b)
                    cpa4(smem_u32(&s_in[nb][u_b * SI_STRIDE + j_b]), ip + off_b, v_b ? 4 : 0);
                cpa16(smem_u32(&s_Uw[nb][tid * 4]), Uw + (size_t)cp * 1024 + tid * 4);
            }
            cpcommit();        // always commit (possibly empty group) to keep count
        }

        // load 4x4 window, transform: V = Bt d B
        float d[4][4];
        {
            const float* si = s_in[cur] + 2 * lane;
#pragma unroll
            for (int u = 0; u < 4; u++) {
                float2 xa = *(const float2*)(si + u * SI_STRIDE);
                float2 xb = *(const float2*)(si + u * SI_STRIDE + 2);
                d[u][0] = xa.x; d[u][1] = xa.y; d[u][2] = xb.x; d[u][3] = xb.y;
            }
        }
#pragma unroll
        for (int j = 0; j < 4; j++) {
            float a0 = d[0][j], a1 = d[1][j], a2 = d[2][j], a3 = d[3][j];
            d[0][j] = a0 - a2;
            d[1][j] = a1 + a2;
            d[2][j] = a2 - a1;
            d[3][j] = a1 - a3;
        }
        u64 V2[8];
#pragma unroll
        for (int i = 0; i < 4; i++) {
            float a0 = d[i][0], a1 = d[i][1], a2 = d[i][2], a3 = d[i][3];
            V2[2 * i]     = pk2(a0 - a2, a1 + a2);
            V2[2 * i + 1] = pk2(a2 - a1, a1 - a3);
        }

#pragma unroll
        for (int o = 0; o < 8; o++) {
            const ulonglong2* Up = (const ulonglong2*)(s_Uw[cur] + (obase + o) * 16);
            ulonglong2 uA = Up[0], uB = Up[1], uC = Up[2], uD = Up[3];
            ffma2(acc[o][0], uA.x, V2[0]);
            ffma2(acc[o][1], uA.y, V2[1]);
            ffma2(acc[o][2], uB.x, V2[2]);
            ffma2(acc[o][3], uB.y, V2[3]);
            ffma2(acc[o][4], uC.x, V2[4]);
            ffma2(acc[o][5], uC.y, V2[5]);
            ffma2(acc[o][6], uD.x, V2[6]);
            ffma2(acc[o][7], uD.y, V2[7]);
        }
    }

    // inverse transform Y = At M A, add const, BN, ReLU, store
#pragma unroll
    for (int o = 0; o < 8; o++) {
        int oc = obase + o;
        float m[16];
#pragma unroll
        for (int k = 0; k < 8; k++) upk2(acc[o][k], m[2 * k], m[2 * k + 1]);
        float z0[4], z1[4];
#pragma unroll
        for (int j = 0; j < 4; j++) {
            z0[j] = m[j] + m[4 + j] + m[8 + j];
            z1[j] = m[4 + j] - m[8 + j] - m[12 + j];
        }
        float y00 = z0[0] + z0[1] + z0[2];
        float y01 = z0[1] - z0[2] - z0[3];
        float y10 = z1[0] + z1[1] + z1[2];
        float y11 = z1[1] - z1[2] - z1[3];

        y00 += Tadd.t(oc, 0, 0); y01 += Tadd.t(oc, 0, 1);
        y10 += Tadd.t(oc, 1, 0); y11 += Tadd.t(oc, 1, 1);

        float s = gg[oc] * rsqrtf(vv[oc] + 1e-5f);
        float t = fmaf(s, bb[oc] - mm[oc], bee[oc]);
        float2 r0, r1;
        r0.x = fmaxf(fmaf(s, y00, t), 0.f);
        r0.y = fmaxf(fmaf(s, y01, t), 0.f);
        r1.x = fmaxf(fmaf(s, y10, t), 0.f);
        r1.y = fmaxf(fmaf(s, y11, t), 0.f);
        size_t base = ((size_t)(b * CC + oc) * HH + h0) * WW + w0 + 2 * lane;
        *(float2*)(out + base) = r0;
        *(float2*)(out + base + WW) = r1;
    }
}

__global__ void __launch_bounds__(256, 1)
convW(const float* __restrict__ in, int CI, const float* __restrict__ Uw,
      const float* __restrict__ bb, const float* __restrict__ gg,
      const float* __restrict__ bee, const float* __restrict__ mm,
      const float* __restrict__ vv, float* __restrict__ out)
{
    SrcPlain src;
    src.base = in + (size_t)blockIdx.z * CI * HW;
    convW_body(src, CI, Uw, bb, gg, bee, mm, vv, out, NoT());
}

__global__ void __launch_bounds__(256, 1)
convWa(const float* __restrict__ enc, const float* __restrict__ img,
       const float* __restrict__ Uw,
       const float* __restrict__ bb, const float* __restrict__ gg,
       const float* __restrict__ bee, const float* __restrict__ mm,
       const float* __restrict__ vv, float* __restrict__ out)
{
    const int b = blockIdx.z;
    __shared__ float s_T[576];
    for (int idx = threadIdx.x; idx < 576; idx += 256)
        s_T[idx] = g_T[(size_t)b * 576 + idx];
    __syncthreads();

    const int w0 = blockIdx.x * 64, h0 = blockIdx.y * 2;
    const int lane = threadIdx.x & 31;
    const int colA = w0 + 2 * lane, colB = colA + 1;
    WaT wt;
    wt.T9 = s_T;
    wt.cy0 = (h0 == 0) ? 0 : 1;
    wt.cy1 = (h0 + 1 == HH - 1) ? 2 : 1;
    wt.cxA = (colA == 0) ? 0 : ((colA == WW - 1) ? 2 : 1);
    wt.cxB = (colB == WW - 1) ? 2 : 1;

    SrcWa src;
    src.enc = enc + (size_t)b * CC * HW;
    src.img = img + (size_t)b * 3 * HW;
    convW_body(src, 67, Uw, bb, gg, bee, mm, vv, out, wt);
}

// ---------------- msg contribution T[b][o][case] ---------------------------
__global__ void msgT(const float* __restrict__ msg, const float* __restrict__ wa)
{
    int o = blockIdx.x, b = blockIdx.y, l = threadIdx.x;
    __shared__ float S[9][256];
    float m = msg[b * LL + l];
    const float* wp = wa + ((size_t)o * 323 + l) * 9;
#pragma unroll
    for (int k = 0; k < 9; k++) S[k][l] = m * wp[k];
    __syncthreads();
    for (int s = 128; s > 0; s >>= 1) {
        if (l < s) {
#pragma unroll
            for (int k = 0; k < 9; k++) S[k][l] += S[k][l + s];
        }
        __syncthreads();
    }
    if (l == 0) {
        float P[9];
#pragma unroll
        for (int k = 0; k < 9; k++) P[k] = S[k][0];
        for (int cy = 0; cy < 3; cy++)
            for (int cx = 0; cx < 3; cx++) {
                float t = 0.f;
                for (int ky = 0; ky < 3; ky++) {
                    if (!(cy == 1 || (cy == 0 && ky >= 1) || (cy == 2 && ky <= 1))) continue;
                    for (int kx = 0; kx < 3; kx++) {
                        if (!(cx == 1 || (cx == 0 && kx >= 1) || (cx == 2 && kx <= 1))) continue;
                        t += P[ky * 3 + kx];
                    }
                }
                g_T[((size_t)b * CC + o) * 9 + cy * 3 + cx] = t;
            }
    }
}

// ---------------- watermark: sparse-frequency fft edit ---------------------
__global__ void kG(const float* __restrict__ x)
{
    int h = blockIdx.x, b = blockIdx.y, lane = threadIdx.x;
    __shared__ float ct[256], st[256];
    for (int i = lane; i < 256; i += 32) {
        float s, c;
        sincosf(6.283185307179586f * (float)i / 256.f, &s, &c);
        ct[i] = c; st[i] = s;
    }
    __syncthreads();
    const float* xp = x + ((size_t)(b * CC) * HH + h) * WW;
    float gr[21], gi[21];
#pragma unroll
    for (int j = 0; j < 21; j++) { gr[j] = 0.f; gi[j] = 0.f; }
    for (int w = lane; w < WW; w += 32) {
        float v = xp[w];
#pragma unroll
        for (int j = 0; j < 21; j++) {
            int idx = ((118 + j) * w) & 255;
            gr[j] = fmaf(v, ct[idx], gr[j]);
            gi[j] = fmaf(-v, st[idx], gi[j]);
        }
    }
#pragma unroll
    for (int j = 0; j < 21; j++) {
        for (int off = 16; off; off >>= 1) {
            gr[j] += __shfl_down_sync(0xffffffffu, gr[j], off);
            gi[j] += __shfl_down_sync(0xffffffffu, gi[j], off);
        }
    }
    if (lane == 0) {
#pragma unroll
        for (int j = 0; j < 21; j++)
            g_G[((size_t)b * HH + h) * 21 + j] = make_float2(gr[j], gi[j]);
    }
}

__global__ void kF(const float* __restrict__ msg)
{
    int b = blockIdx.x, l = threadIdx.x;
    __shared__ float ct[256], st[256];
    {
        float s, c;
        sincosf(6.283185307179586f * (float)l / 256.f, &s, &c);
        ct[l] = c; st[l] = s;
    }
    __syncthreads();
    int dy = g_dy[l], dx = g_dx[l];
    int jx = dx + 10, yy = 128 + dy;
    float fr = 0.f, fi = 0.f;
    for (int h = 0; h < HH; h++) {
        float2 G = g_G[((size_t)b * HH + h) * 21 + jx];
        int idx = (yy * h) & 255;
        float c = ct[idx], s = st[idx];
        fr += G.x * c + G.y * s;
        fi += G.y * c - G.x * s;
    }
    float m = msg[b * LL + l];
    g_delta[b * LL + l] = make_float2(m - fr, m - fi);
}

__global__ void kU()
{
    int iy = blockIdx.x, b = blockIdx.y, w = threadIdx.x;
    __shared__ float ct[256], st[256], dr[256], di[256];
    __shared__ int sdx[256], sdy[256];
    {
        float s, c;
        sincosf(6.283185307179586f * (float)w / 256.f, &s, &c);
        ct[w] = c; st[w] = s;
        float2 d = g_delta[b * LL + w];
        dr[w] = d.x; di[w] = d.y;
        sdx[w] = g_dx[w]; sdy[w] = g_dy[w];
    }
    __syncthreads();
    float ur = 0.f, ui = 0.f;
    for (int l = 0; l < LL; l++) {
        if (sdy[l] + 10 == iy) {
            int idx = ((128 + sdx[l]) * w) & 255;
            float c = ct[idx], s = st[idx];
            ur += dr[l] * c - di[l] * s;
            ui += dr[l] * s + di[l] * c;
        }
    }
    g_U[((size_t)b * 21 + iy) * WW + w] = make_float2(ur, ui);
}

__global__ void kAdd(float* __restrict__ x)
{
    int h = blockIdx.x, b = blockIdx.y, w = threadIdx.x;
    __shared__ float ct[256], st[256];
    {
        float s, c;
        sincosf(6.283185307179586f * (float)w / 256.f, &s, &c);
        ct[w] = c; st[w] = s;
    }
    __syncthreads();
    float a = 0.f;
#pragma unroll
    for (int iy = 0; iy < 21; iy++) {
        int idx = ((118 + iy) * h) & 255;
        float2 U = g_U[((size_t)b * 21 + iy) * WW + w];
        a += U.x * ct[idx] - U.y * st[idx];
    }
    size_t off = ((size_t)(b * CC) * HH + h) * WW + w;
    x[off] += a * (1.f / 65536.f);
}

// ---------------- final 1x1 projection 64 -> 3 -----------------------------
__global__ void final1x1(const float* __restrict__ y, const float* __restrict__ wf,
                         const float* __restrict__ bf, float* __restrict__ out)
{
    int w = threadIdx.x, h = blockIdx.x, b = blockIdx.y;
    __shared__ float swf[192];
    __shared__ float sbf[3];
    if (threadIdx.x < 192) swf[threadIdx.x] = wf[threadIdx.x];
    if (threadIdx.x < 3) sbf[threadIdx.x] = bf[threadIdx.x];
    __syncthreads();
    float a0 = sbf[0], a1 = sbf[1], a2 = sbf[2];
    const float* yp = y + ((size_t)(b * CC) * HH + h) * WW + w;
#pragma unroll 8
    for (int c = 0; c < 64; c++) {
        float v = yp[(size_t)c * HW];
        a0 = fmaf(v, swf[c], a0);
        a1 = fmaf(v, swf[64 + c], a1);
        a2 = fmaf(v, swf[128 + c], a2);
    }
    size_t o = ((size_t)(b * 3) * HH + h) * WW + w;
    out[o] = a0;
    out[o + (size_t)HW] = a1;
    out[o + (size_t)2 * HW] = a2;
}

// ---------------- launcher -------------------------------------------------
extern "C" void kernel_launch(void* const* d_in, const int* in_sizes, int n_in,
                              void* d_out, int out_size)
{
    const float* image   = (const float*)d_in[0];
    const float* message = (const float*)d_in[1];
    const float* w0  = (const float*)d_in[2];
    const float* b0  = (const float*)d_in[3];
    const float* g0  = (const float*)d_in[4];
    const float* be0 = (const float*)d_in[5];
    const float* m0  = (const float*)d_in[6];
    const float* v0  = (const float*)d_in[7];
    const float* wk  = (const float*)d_in[8];
    const float* bk  = (const float*)d_in[9];
    const float* gk  = (const float*)d_in[10];
    const float* bek = (const float*)d_in[11];
    const float* mk  = (const float*)d_in[12];
    const float* vk  = (const float*)d_in[13];
    const float* wa  = (const float*)d_in[14];
    const float* ba  = (const float*)d_in[15];
    const float* ga  = (const float*)d_in[16];
    const float* bea = (const float*)d_in[17];
    const float* ma  = (const float*)d_in[18];
    const float* va  = (const float*)d_in[19];
    const float* wf  = (const float*)d_in[20];
    const float* bf  = (const float*)d_in[21];

    float* bufA = nullptr;
    float* bufB = nullptr;
    float* Uw = nullptr;
    cudaGetSymbolAddress((void**)&bufA, g_bufA);
    cudaGetSymbolAddress((void**)&bufB, g_bufB);
    cudaGetSymbolAddress((void**)&Uw, g_wU);

    // launch 1: all prep (indices + weight transforms)
    prepU<<<66, 256>>>(w0, wk, wa, Uw);
    // launch 2: message contribution (independent of convs)
    msgT<<<dim3(64, BB), 256>>>(message, wa);

    dim3 cgrid(WW / 64, HH / 2, BB);
    // launches 3-6 (launch 6 = conv layer 3, captured by ncu -s 5)
    convW<<<cgrid, 256>>>(image, 3, Uw + U_O0, b0, g0, be0, m0, v0, bufA);
    convW<<<cgrid, 256>>>(bufA, 64, Uw + U_O1, bk,       gk,       bek,       mk,       vk,       bufB);
    convW<<<cgrid, 256>>>(bufB, 64, Uw + U_O2, bk + 64,  gk + 64,  bek + 64,  mk + 64,  vk + 64,  bufA);
    convW<<<cgrid, 256>>>(bufA, 64, Uw + U_O3, bk + 128, gk + 128, bek + 128, mk + 128, vk + 128, bufB);

    // watermark (modifies channel 0 of bufB in place)
    kG<<<dim3(HH, BB), 32>>>(bufB);
    kF<<<BB, 256>>>(message);
    kU<<<dim3(21, BB), 256>>>();
    kAdd<<<dim3(HH, BB), 256>>>(bufB);

    convWa<<<cgrid, 256>>>(bufB, image, Uw + U_O4, ba, ga, bea, ma, va, bufA);

    final1x1<<<dim3(HH, BB), 256>>>(bufA, wf, bf, (float*)d_out);
}